// round 6
// baseline (speedup 1.0000x reference)
#include <cuda_runtime.h>

#define GN    6
#define NN    36
#define NB7   7            // 7x7 counter grid incl. trash row/col
#define NPED  8192
#define HID   128
#define RPB   128          // rows per count block
#define NSL   16           // j-slices
#define JCH   (NPED / NSL) // 512
#define HROW  (NPED / 2)   // u32 words per bin (2 u16 rows per word)

// Global counts, u16-packed row pairs: g16[c*HROW + i/2] = cnt(i) | cnt(i+1)<<16.
// Zero-initialized at load; count_kernel REDs into it, embed_kernel reads each
// word exactly once and re-zeroes it -> invariant holds across graph replays.
__device__ unsigned g16[NN * HROW];   // 576 KB

// ---------------------------------------------------------------------------
// Phase 1: branch-free occupancy histogram, conflict-free u32 counters.
// Every pair unconditionally increments; out-of-range lands in trash bins
// (bx==6 or by==6) which are never flushed.
// ---------------------------------------------------------------------------
__global__ __launch_bounds__(RPB) void count_kernel(const float* __restrict__ obs2) {
    __shared__ unsigned   cnt[NB7 * NB7 * RPB];  // [bin49][t], bank = t%32 (conflict-free)
    __shared__ ulonglong2 pts[JCH / 2];          // 2 points per element, 4 KB

    const int t  = threadIdx.x;
    const int i  = blockIdx.x * RPB + t;
    const int j0 = blockIdx.y * JCH;

    // Stage slice points (128B loads)
    {
        const ulonglong2* src = (const ulonglong2*)(obs2 + 2 * j0);
#pragma unroll
        for (int k = 0; k < JCH / 2 / RPB; k++)
            pts[t + k * RPB] = src[t + k * RPB];
    }
    // Zero counters: 49 words per thread
#pragma unroll
    for (int k = 0; k < NB7 * NB7; k++)
        cnt[k * RPB + t] = 0u;

    const float2 pi = ((const float2*)obs2)[i];
    float nx = -pi.x, ny = -pi.y;
    unsigned long long negpi;
    asm("mov.b64 %0, {%1,%2};" : "=l"(negpi) : "f"(nx), "f"(ny));
    const unsigned long long THREE2 = 0x4040000040400000ULL;  // (3.0f, 3.0f)
    const float MAGIC = 8388608.0f;                           // 2^23

    __syncthreads();

    unsigned* mycnt = cnt + t;

#pragma unroll 4
    for (int k = 0; k < JCH / 2; k++) {
        const ulonglong2 pp = pts[k];   // LDS.128: two points, warp-uniform
#pragma unroll
        for (int half = 0; half < 2; half++) {
            const unsigned long long pj = half ? pp.y : pp.x;
            unsigned long long d, e;
            // EXACT reference order per lane: rn(pj - pi), then rn(+3)
            asm("add.rn.f32x2 %0, %1, %2;" : "=l"(d) : "l"(pj), "l"(negpi));
            asm("add.rn.f32x2 %0, %1, %2;" : "=l"(e) : "l"(d), "l"(THREE2));
            const float ex = __uint_as_float((unsigned)e);
            const float ey = __uint_as_float((unsigned)(e >> 32));
            float fx, fy;
            asm("add.rm.f32 %0, %1, %2;" : "=f"(fx) : "f"(ex), "f"(MAGIC));
            asm("add.rm.f32 %0, %1, %2;" : "=f"(fy) : "f"(ey), "f"(MAGIC));
            unsigned bx = __float_as_uint(fx) - 0x4B000000u;  // floor; OOR -> huge
            unsigned by = __float_as_uint(fy) - 0x4B000000u;
            bx = umin(bx, 6u);
            by = umin(by, 6u);
            mycnt[(bx * NB7 + by) * RPB] += 1u;  // conflict-free RMW, no branch
        }
    }

    __syncthreads();  // flush reads other threads' counter columns

    // Flush 36 valid bins as u16-packed row pairs: 36*64 = 2304 words, 18/thread.
    // Each g16 word receives one RED from each of the 16 j-slice blocks.
#pragma unroll
    for (int k = 0; k < 18; k++) {
        const int gidx = k * RPB + t;     // 0..2303
        const int vb   = gidx >> 6;       // valid bin 0..35
        const int w    = gidx & 63;       // row-pair within this i-block
        const int b49  = (vb / GN) * NB7 + (vb % GN);
        const unsigned lo = cnt[b49 * RPB + 2 * w];
        const unsigned hi = cnt[b49 * RPB + 2 * w + 1];
        const unsigned v  = lo | (hi << 16);
        if (v)
            asm volatile("red.global.add.u32 [%0], %1;"
                         :: "l"(&g16[vb * HROW + blockIdx.x * (RPB / 2) + w]),
                            "r"(v) : "memory");
    }
}

// ---------------------------------------------------------------------------
// Phase 2: read packed counts (re-zeroing for the next replay), remove the
// self pair (always bin 21), linear embedding. 1024 blocks x 128 thr.
// ---------------------------------------------------------------------------
__global__ __launch_bounds__(HID) void embed_kernel(const float* __restrict__ W,
                                                    const float* __restrict__ b,
                                                    float* __restrict__ out) {
    __shared__ float cs[8][NN];   // reduced counts for this block's 8 rows

    const int t  = threadIdx.x;
    const int i0 = blockIdx.x * 8;

    // 36 bins x 4 row-pair words = 144 read+rezero tasks
    for (int task = t; task < NN * 4; task += HID) {
        const int c = task >> 2;
        const int w = task & 3;
        unsigned* p = &g16[c * HROW + (i0 >> 1) + w];
        const unsigned v = *p;
        *p = 0u;                              // restore zero for next replay
        const unsigned self = (c == 3 * GN + 3) ? 1u : 0u;
        cs[2 * w + 0][c] = (float)((v & 0xFFFFu) - self);
        cs[2 * w + 1][c] = (float)((v >> 16) - self);
    }
    __syncthreads();

    // One thread per h: W row = 36 consecutive floats = 9 float4 (16B-aligned)
    const int h = t;
    float w[NN];
    {
        const float4* Wv = (const float4*)(W + h * NN);
#pragma unroll
        for (int q = 0; q < NN / 4; q++) {
            const float4 v = Wv[q];
            w[4 * q + 0] = v.x; w[4 * q + 1] = v.y;
            w[4 * q + 2] = v.z; w[4 * q + 3] = v.w;
        }
    }
    const float bh = b[h];

#pragma unroll
    for (int r = 0; r < 8; r++) {
        float acc = bh;
#pragma unroll
        for (int c = 0; c < NN; c++)
            acc = fmaf(cs[r][c], w[c], acc);   // cs broadcast LDS
        out[(i0 + r) * HID + h] = acc;         // coalesced
    }
}

// ---------------------------------------------------------------------------
// Inputs: 0 hidden_state (unused), 1 obs1 (unused), 2 obs2 [8192,2],
// 3 W [128,36], 4 b [128]. Output fp32 [8192,128].
// ---------------------------------------------------------------------------
extern "C" void kernel_launch(void* const* d_in, const int* in_sizes, int n_in,
                              void* d_out, int out_size) {
    const float* obs2 = (const float*)d_in[2];
    const float* W    = (const float*)d_in[3];
    const float* b    = (const float*)d_in[4];
    float*       out  = (float*)d_out;

    dim3 g1(NPED / RPB, NSL);        // 64 x 16 = 1024 blocks
    count_kernel<<<g1, RPB>>>(obs2);
    embed_kernel<<<NPED / 8, HID>>>(W, b, out);
}